// round 12
// baseline (speedup 1.0000x reference)
#include <cuda_runtime.h>
#include <cuda_fp16.h>
#include <cstdint>

// ---------------------------------------------------------------------------
// ViT encoder block. GEMMs: single-pass fp16 mma.sync (fp32 accumulate),
// 128x128 CTA tile, 32x64 warp tile, BK=32 (32 MMAs per barrier),
// register-prefetch double-buffered smem. Merged QKV.
// Attention + LayerNorm fp32 SIMT.
// ---------------------------------------------------------------------------

#define NTOK   16384
#define EMB    768
#define FFND   3072
#define HEADS  12
#define DK     64
#define SEQ    512
#define BATCH  32
#define QKVN   2304

// ----- fp32 scratch -----
__device__ __align__(128) float g_qkv[NTOK * QKVN];
__device__ __align__(128) float g_tmp[NTOK * EMB];
__device__ __align__(128) float g_x1 [NTOK * EMB];

// ----- fp16 scratch -----
__device__ __align__(128) __half g_ah[NTOK * EMB];    // activations (x, then x1)
__device__ __align__(128) __half g_ch[NTOK * EMB];    // ctx
__device__ __align__(128) __half g_fh[NTOK * FFND];   // relu(ffn)
#define WTOT 7077888
__device__ __align__(128) __half g_wh[WTOT];          // all weights, QKV merged

// ===========================================================================
// helpers
// ===========================================================================
__device__ __forceinline__ void ldsm4(uint32_t* r, const void* p) {
    uint32_t a = (uint32_t)__cvta_generic_to_shared(p);
    asm volatile("ldmatrix.sync.aligned.m8n8.x4.shared.b16 {%0,%1,%2,%3}, [%4];"
                 : "=r"(r[0]), "=r"(r[1]), "=r"(r[2]), "=r"(r[3]) : "r"(a));
}
__device__ __forceinline__ void ldsm4t(uint32_t* r, const void* p) {
    uint32_t a = (uint32_t)__cvta_generic_to_shared(p);
    asm volatile("ldmatrix.sync.aligned.m8n8.x4.trans.shared.b16 {%0,%1,%2,%3}, [%4];"
                 : "=r"(r[0]), "=r"(r[1]), "=r"(r[2]), "=r"(r[3]) : "r"(a));
}
__device__ __forceinline__ void mma16816(float* c, const uint32_t* a, const uint32_t* b) {
    asm volatile("mma.sync.aligned.m16n8k16.row.col.f32.f16.f16.f32 "
                 "{%0,%1,%2,%3}, {%4,%5,%6,%7}, {%8,%9}, {%0,%1,%2,%3};"
                 : "+f"(c[0]), "+f"(c[1]), "+f"(c[2]), "+f"(c[3])
                 : "r"(a[0]), "r"(a[1]), "r"(a[2]), "r"(a[3]), "r"(b[0]), "r"(b[1]));
}

// ===========================================================================
// cvt: fp32 -> fp16 (contiguous, for activations)
// ===========================================================================
__global__ __launch_bounds__(256) void cvt_kernel(
    const float* __restrict__ in, __half* __restrict__ h, int n)
{
    int i = (blockIdx.x * 256 + threadIdx.x) * 8;
    if (i >= n) return;
    float4 v0 = *(const float4*)(in + i);
    float4 v1 = *(const float4*)(in + i + 4);
    *reinterpret_cast<__half2*>(h + i)     = __floats2half2_rn(v0.x, v0.y);
    *reinterpret_cast<__half2*>(h + i + 2) = __floats2half2_rn(v0.z, v0.w);
    *reinterpret_cast<__half2*>(h + i + 4) = __floats2half2_rn(v1.x, v1.y);
    *reinterpret_cast<__half2*>(h + i + 6) = __floats2half2_rn(v1.z, v1.w);
}

// ===========================================================================
// cvtw: W[K,N] fp32 -> fp16 at column offset `off` of width-Ntot buffer
// ===========================================================================
__global__ __launch_bounds__(256) void cvtw_kernel(
    const float* __restrict__ W, __half* __restrict__ h,
    int N, int Ntot, int off, int total)
{
    int i = (blockIdx.x * 256 + threadIdx.x) * 4;
    if (i >= total) return;
    int k = i / N, n = i - k * N;
    size_t o = (size_t)k * Ntot + off + n;
    float4 v = *(const float4*)(W + i);
    *reinterpret_cast<__half2*>(h + o)     = __floats2half2_rn(v.x, v.y);
    *reinterpret_cast<__half2*>(h + o + 2) = __floats2half2_rn(v.z, v.w);
}

// ===========================================================================
// GEMM: C[M,N] = A[M,K] @ B[K,N]; A/B fp16. 128x128 tile, BK=32,
// 256 threads (4x2 warps, 32x64 per warp), register prefetch + double buffer,
// 32 MMAs per barrier (2 k-slices of 16).
// EPI: 0 = fp32 C; 1 = +bias fp32 C; 3 = +bias+relu -> fp16 Ch
// ===========================================================================
#define ASTR 40    // A smem row stride (elems): 32 + 8 pad
#define BSTR 136   // B smem row stride (elems): 128 + 8 pad

template <int EPI>
__global__ __launch_bounds__(256) void tgemm(
    const __half* __restrict__ A, const __half* __restrict__ B,
    const float* __restrict__ bias, float* __restrict__ C,
    __half* __restrict__ Ch,
    int M, int N, int K)
{
    __shared__ __align__(16) __half sA[2][128 * ASTR];
    __shared__ __align__(16) __half sB[2][32 * BSTR];

    const int tid  = threadIdx.x;
    const int lane = tid & 31;
    const int w    = tid >> 5;
    const int wm   = w & 3;
    const int wn   = w >> 2;
    const int bm   = blockIdx.y * 128;
    const int bn   = blockIdx.x * 128;

    // A loader: thread -> (row ar, 16 cols at ac)
    const int ar = tid >> 1;           // 0..127
    const int ac = (tid & 1) * 16;     // 0 or 16
    // B loader: thread -> (row br, 16 cols at bc)
    const int br = tid >> 3;           // 0..31
    const int bc = (tid & 7) * 16;     // 0..112

    const __half* gA = A + (size_t)(bm + ar) * K + ac;
    const __half* gB = B + (size_t)br * N + bn + bc;

    // ldmatrix element offsets for k-slice 0; slice 1 adds +16 (A) / +16*BSTR (B)
    int a_off[2];
#pragma unroll
    for (int mi = 0; mi < 2; mi++) {
        int row = wm * 32 + mi * 16 + (lane & 15);
        int col = (lane >> 4) * 8;
        a_off[mi] = row * ASTR + col;
    }
    int b_off[4];
    {
        int krow = lane & 15;
#pragma unroll
        for (int p = 0; p < 4; p++) {
            int col = wn * 64 + (p * 2 + (lane >> 4)) * 8;
            b_off[p] = krow * BSTR + col;
        }
    }

    float c[2][8][4];
#pragma unroll
    for (int mi = 0; mi < 2; mi++)
#pragma unroll
        for (int ni = 0; ni < 8; ni++)
#pragma unroll
            for (int e = 0; e < 4; e++) c[mi][ni][e] = 0.f;

    // prologue: tile 0 -> buf 0
    {
        uint4 a0 = *(const uint4*)(gA);
        uint4 a1 = *(const uint4*)(gA + 8);
        uint4 b0 = *(const uint4*)(gB);
        uint4 b1 = *(const uint4*)(gB + 8);
        *(uint4*)&sA[0][ar * ASTR + ac]     = a0;
        *(uint4*)&sA[0][ar * ASTR + ac + 8] = a1;
        *(uint4*)&sB[0][br * BSTR + bc]     = b0;
        *(uint4*)&sB[0][br * BSTR + bc + 8] = b1;
    }
    __syncthreads();

    const int nk = K >> 5;
    uint4 pa0, pa1, pb0, pb1;
    for (int kt = 0; kt < nk; kt++) {
        const int buf = kt & 1;
        if (kt + 1 < nk) {
            int k0 = (kt + 1) * 32;
            pa0 = *(const uint4*)(gA + k0);
            pa1 = *(const uint4*)(gA + k0 + 8);
            pb0 = *(const uint4*)(gB + (size_t)k0 * N);
            pb1 = *(const uint4*)(gB + (size_t)k0 * N + 8);
        }

#pragma unroll
        for (int ks = 0; ks < 2; ks++) {
            uint32_t fa[2][4], fb[8][2];
#pragma unroll
            for (int mi = 0; mi < 2; mi++)
                ldsm4(fa[mi], &sA[buf][a_off[mi] + ks * 16]);
#pragma unroll
            for (int p = 0; p < 4; p++) {
                uint32_t r[4];
                ldsm4t(r, &sB[buf][b_off[p] + ks * 16 * BSTR]);
                fb[p * 2][0] = r[0]; fb[p * 2][1] = r[1];
                fb[p * 2 + 1][0] = r[2]; fb[p * 2 + 1][1] = r[3];
            }
#pragma unroll
            for (int mi = 0; mi < 2; mi++)
#pragma unroll
                for (int ni = 0; ni < 8; ni++) mma16816(c[mi][ni], fa[mi], fb[ni]);
        }

        if (kt + 1 < nk) {
            const int nb = buf ^ 1;
            *(uint4*)&sA[nb][ar * ASTR + ac]     = pa0;
            *(uint4*)&sA[nb][ar * ASTR + ac + 8] = pa1;
            *(uint4*)&sB[nb][br * BSTR + bc]     = pb0;
            *(uint4*)&sB[nb][br * BSTR + bc + 8] = pb1;
            __syncthreads();
        }
    }

    // epilogue
    const int er = lane >> 2;
    const int ec = (lane & 3) * 2;
#pragma unroll
    for (int mi = 0; mi < 2; mi++) {
#pragma unroll
        for (int ni = 0; ni < 8; ni++) {
            int r0 = bm + wm * 32 + mi * 16 + er;
            int cc = bn + wn * 64 + ni * 8 + ec;
            float v0 = c[mi][ni][0], v1 = c[mi][ni][1];
            float v2 = c[mi][ni][2], v3 = c[mi][ni][3];
            if (EPI >= 1) {
                float bi0 = bias[cc], bi1 = bias[cc + 1];
                v0 += bi0; v1 += bi1; v2 += bi0; v3 += bi1;
            }
            if (EPI == 3) {
                v0 = fmaxf(v0, 0.f); v1 = fmaxf(v1, 0.f);
                v2 = fmaxf(v2, 0.f); v3 = fmaxf(v3, 0.f);
                *reinterpret_cast<__half2*>(&Ch[(size_t)r0 * N + cc]) =
                    __floats2half2_rn(v0, v1);
                *reinterpret_cast<__half2*>(&Ch[(size_t)(r0 + 8) * N + cc]) =
                    __floats2half2_rn(v2, v3);
            } else {
                *(float2*)&C[(size_t)r0 * N + cc]       = make_float2(v0, v1);
                *(float2*)&C[(size_t)(r0 + 8) * N + cc] = make_float2(v2, v3);
            }
        }
    }
}

// ===========================================================================
// Attention (fp32 SIMT) reading fused QKV [NTOK, 2304]; ctx -> fp16.
// ===========================================================================
__global__ __launch_bounds__(256) void attn_kernel(
    const float* __restrict__ QKV, __half* __restrict__ Oh)
{
    extern __shared__ float sm[];
    float* sQ  = sm;
    float* sK  = sQ + 2048;
    float* sKt = sK + 4096;
    float* sS  = sKt + 4352;

    const int qt  = blockIdx.x;
    const int h   = blockIdx.y;
    const int b   = blockIdx.z;
    const int tid = threadIdx.x;
    const size_t base = (size_t)b * SEQ * QKVN + h * DK;

    for (int i = tid; i < 512; i += 256) {
        int r = i >> 4, cx = (i & 15) * 4;
        *(float4*)&sQ[r * 64 + cx] =
            *(const float4*)&QKV[base + (size_t)(qt * 32 + r) * QKVN + cx];
    }

    const int gq  = tid >> 4;
    const int gk  = tid & 15;
    const int qi0 = gq * 2;
    const int kj0 = gk * 4;

    for (int kt = 0; kt < 8; kt++) {
        __syncthreads();
        for (int i = tid; i < 1024; i += 256) {
            int r = i >> 4, cx = (i & 15) * 4;
            *(float4*)&sK[r * 64 + cx] =
                *(const float4*)&QKV[base + 768 + (size_t)(kt * 64 + r) * QKVN + cx];
        }
        __syncthreads();
        for (int i = tid; i < 4096; i += 256) {
            int d = i & 63, r = i >> 6;
            sKt[d * 68 + r] = sK[r * 64 + d];
        }
        __syncthreads();

        float acc[2][4] = {{0.f,0.f,0.f,0.f},{0.f,0.f,0.f,0.f}};
#pragma unroll 8
        for (int d = 0; d < 64; d++) {
            float q0 = sQ[qi0 * 64 + d];
            float q1 = sQ[qi0 * 64 + 64 + d];
            float4 kv = *(float4*)&sKt[d * 68 + kj0];
            acc[0][0] += q0 * kv.x; acc[0][1] += q0 * kv.y;
            acc[0][2] += q0 * kv.z; acc[0][3] += q0 * kv.w;
            acc[1][0] += q1 * kv.x; acc[1][1] += q1 * kv.y;
            acc[1][2] += q1 * kv.z; acc[1][3] += q1 * kv.w;
        }
#pragma unroll
        for (int i = 0; i < 2; i++)
#pragma unroll
            for (int j = 0; j < 4; j++)
                sS[(qi0 + i) * 512 + kt * 64 + kj0 + j] = acc[i][j] * 0.125f;
    }
    __syncthreads();

    {
        const int wid = tid >> 5, lanei = tid & 31;
        for (int r = wid * 4; r < wid * 4 + 4; r++) {
            float* srow = sS + r * 512;
            float m = -1e30f;
            for (int cx = lanei; cx < 512; cx += 32) m = fmaxf(m, srow[cx]);
#pragma unroll
            for (int o = 16; o > 0; o >>= 1)
                m = fmaxf(m, __shfl_xor_sync(0xffffffffu, m, o));
            float s = 0.f;
            for (int cx = lanei; cx < 512; cx += 32) {
                float e = __expf(srow[cx] - m);
                srow[cx] = e;
                s += e;
            }
#pragma unroll
            for (int o = 16; o > 0; o >>= 1)
                s += __shfl_xor_sync(0xffffffffu, s, o);
            float inv = 1.0f / s;
            for (int cx = lanei; cx < 512; cx += 32) srow[cx] *= inv;
        }
    }

    const int d0 = gk * 4;
    float o_[2][4] = {{0.f,0.f,0.f,0.f},{0.f,0.f,0.f,0.f}};
    for (int kt = 0; kt < 8; kt++) {
        __syncthreads();
        for (int i = tid; i < 1024; i += 256) {
            int r = i >> 4, cx = (i & 15) * 4;
            *(float4*)&sK[r * 64 + cx] =
                *(const float4*)&QKV[base + 1536 + (size_t)(kt * 64 + r) * QKVN + cx];
        }
        __syncthreads();
#pragma unroll 4
        for (int k = 0; k < 64; k++) {
            float s0 = sS[qi0 * 512 + kt * 64 + k];
            float s1 = sS[qi0 * 512 + 512 + kt * 64 + k];
            float4 vv = *(float4*)&sK[k * 64 + d0];
            o_[0][0] += s0 * vv.x; o_[0][1] += s0 * vv.y;
            o_[0][2] += s0 * vv.z; o_[0][3] += s0 * vv.w;
            o_[1][0] += s1 * vv.x; o_[1][1] += s1 * vv.y;
            o_[1][2] += s1 * vv.z; o_[1][3] += s1 * vv.w;
        }
    }

#pragma unroll
    for (int i = 0; i < 2; i++) {
        size_t idx = ((size_t)b * SEQ + qt * 32 + qi0 + i) * EMB + h * DK + d0;
        *reinterpret_cast<__half2*>(&Oh[idx])     = __floats2half2_rn(o_[i][0], o_[i][1]);
        *reinterpret_cast<__half2*>(&Oh[idx + 2]) = __floats2half2_rn(o_[i][2], o_[i][3]);
    }
}

// ===========================================================================
// Fused residual + LayerNorm (+ optional fp16 out)
// ===========================================================================
__global__ __launch_bounds__(256) void add_ln_kernel(
    const float* __restrict__ x, const float* __restrict__ r,
    const float* __restrict__ gamma, const float* __restrict__ beta,
    float* __restrict__ out, __half* __restrict__ oh)
{
    const int row = blockIdx.x;
    const int tid = threadIdx.x;
    const float* xr = x + (size_t)row * EMB;
    const float* rr = r + (size_t)row * EMB;

    float v[3];
    float s = 0.f;
#pragma unroll
    for (int i = 0; i < 3; i++) {
        int cx = tid + i * 256;
        float t = xr[cx] + rr[cx];
        v[i] = t;
        s += t;
    }

    __shared__ float red[8];
    const int wid = tid >> 5, lane = tid & 31;
#pragma unroll
    for (int o = 16; o > 0; o >>= 1) s += __shfl_xor_sync(0xffffffffu, s, o);
    if (lane == 0) red[wid] = s;
    __syncthreads();
    if (tid == 0) {
        float t = 0.f;
#pragma unroll
        for (int i = 0; i < 8; i++) t += red[i];
        red[0] = t;
    }
    __syncthreads();
    const float mean = red[0] * (1.0f / 768.0f);

    float s2 = 0.f;
#pragma unroll
    for (int i = 0; i < 3; i++) {
        float d = v[i] - mean;
        s2 += d * d;
    }
#pragma unroll
    for (int o = 16; o > 0; o >>= 1) s2 += __shfl_xor_sync(0xffffffffu, s2, o);
    __syncthreads();
    if (lane == 0) red[wid] = s2;
    __syncthreads();
    if (tid == 0) {
        float t = 0.f;
#pragma unroll
        for (int i = 0; i < 8; i++) t += red[i];
        red[0] = t;
    }
    __syncthreads();
    const float var  = red[0] * (1.0f / 768.0f);
    const float rstd = rsqrtf(var + 1e-5f);

#pragma unroll
    for (int i = 0; i < 3; i++) {
        int cx = tid + i * 256;
        float o = (v[i] - mean) * rstd * gamma[cx] + beta[cx];
        size_t idx = (size_t)row * EMB + cx;
        out[idx] = o;
        if (oh) oh[idx] = __float2half_rn(o);
    }
}

// ===========================================================================
// Launch
// ===========================================================================
extern "C" void kernel_launch(void* const* d_in, const int* in_sizes, int n_in,
                              void* d_out, int out_size)
{
    (void)in_sizes; (void)n_in; (void)out_size;

    const float* x   = (const float*)d_in[0];
    const float* Wq  = (const float*)d_in[1];
    const float* Wk  = (const float*)d_in[2];
    const float* Wv  = (const float*)d_in[3];
    const float* Wo  = (const float*)d_in[4];
    const float* W1  = (const float*)d_in[5];
    const float* b1  = (const float*)d_in[6];
    const float* W2  = (const float*)d_in[7];
    const float* b2  = (const float*)d_in[8];
    const float* g1  = (const float*)d_in[9];
    const float* be1 = (const float*)d_in[10];
    const float* g2  = (const float*)d_in[11];
    const float* be2 = (const float*)d_in[12];
    float* out = (float*)d_out;

    float *qkv, *tmp, *x1;
    __half *ah, *ch, *fh, *wh;
    cudaGetSymbolAddress((void**)&qkv, g_qkv);
    cudaGetSymbolAddress((void**)&tmp, g_tmp);
    cudaGetSymbolAddress((void**)&x1,  g_x1);
    cudaGetSymbolAddress((void**)&ah,  g_ah);
    cudaGetSymbolAddress((void**)&ch,  g_ch);
    cudaGetSymbolAddress((void**)&fh,  g_fh);
    cudaGetSymbolAddress((void**)&wh,  g_wh);

    const int ATTN_SMEM = (2048 + 4096 + 64 * 68 + 16384) * 4;
    cudaFuncSetAttribute(attn_kernel,
                         cudaFuncAttributeMaxDynamicSharedMemorySize, ATTN_SMEM);

    const size_t EE = (size_t)EMB * EMB;
    const size_t EF = (size_t)EMB * FFND;
    const size_t OQKV = 0, OO_ = 3 * EE, O1_ = 4 * EE, O2_ = 4 * EE + EF;

    dim3 blk(256);

    // activation conversion (x)
    cvt_kernel<<<NTOK * EMB / 2048, blk>>>(x, ah, NTOK * EMB);
    // weight conversions; Wq/Wk/Wv scatter into merged [768,2304] buffer
    cvtw_kernel<<<(int)(EE / 1024), blk>>>(Wq, wh + OQKV, EMB, QKVN, 0,    (int)EE);
    cvtw_kernel<<<(int)(EE / 1024), blk>>>(Wk, wh + OQKV, EMB, QKVN, 768,  (int)EE);
    cvtw_kernel<<<(int)(EE / 1024), blk>>>(Wv, wh + OQKV, EMB, QKVN, 1536, (int)EE);
    cvtw_kernel<<<(int)(EE / 1024), blk>>>(Wo, wh + OO_,  EMB, EMB,  0,    (int)EE);
    cvtw_kernel<<<(int)(EF / 1024), blk>>>(W1, wh + O1_,  FFND, FFND, 0,   (int)EF);
    cvtw_kernel<<<(int)(EF / 1024), blk>>>(W2, wh + O2_,  EMB,  EMB,  0,   (int)EF);

    // fused QKV projection: [NTOK,768] @ [768,2304]
    tgemm<0><<<dim3(QKVN / 128, NTOK / 128), blk>>>(
        ah, wh + OQKV, nullptr, qkv, nullptr, NTOK, QKVN, EMB);

    // attention -> ctx (fp16)
    attn_kernel<<<dim3(SEQ / 32, HEADS, BATCH), blk, ATTN_SMEM>>>(qkv, ch);

    // output projection
    tgemm<0><<<dim3(EMB / 128, NTOK / 128), blk>>>(
        ch, wh + OO_, nullptr, tmp, nullptr, NTOK, EMB, EMB);

    // residual + LN1 (emits x1 as fp16 into ah)
    add_ln_kernel<<<NTOK, blk>>>(x, tmp, g1, be1, x1, ah);

    // FFN
    tgemm<3><<<dim3(FFND / 128, NTOK / 128), blk>>>(
        ah, wh + O1_, b1, nullptr, fh, NTOK, FFND, EMB);
    tgemm<1><<<dim3(EMB / 128, NTOK / 128), blk>>>(
        fh, wh + O2_, b2, tmp, nullptr, NTOK, EMB, FFND);

    // residual + LN2
    add_ln_kernel<<<NTOK, blk>>>(x1, tmp, g2, be2, out, nullptr);
}

// round 13
// speedup vs baseline: 1.6925x; 1.6925x over previous
#include <cuda_runtime.h>
#include <cuda_fp16.h>
#include <cstdint>

// ---------------------------------------------------------------------------
// ViT encoder block. GEMMs: single-pass fp16 mma.sync (R8 config).
// Attention: fp16 mma.sync, S in registers, register P->A-frag reuse.
// ---------------------------------------------------------------------------

#define NTOK   16384
#define EMB    768
#define FFND   3072
#define HEADS  12
#define DK     64
#define SEQ    512
#define BATCH  32
#define QKVN   2304

// ----- fp32 scratch -----
__device__ __align__(128) float g_tmp[NTOK * EMB];
__device__ __align__(128) float g_x1 [NTOK * EMB];

// ----- fp16 scratch -----
__device__ __align__(128) __half g_qkv[NTOK * QKVN];  // fused QKV (fp16)
__device__ __align__(128) __half g_ah[NTOK * EMB];
__device__ __align__(128) __half g_ch[NTOK * EMB];
__device__ __align__(128) __half g_fh[NTOK * FFND];
#define WTOT 7077888
__device__ __align__(128) __half g_wh[WTOT];

// ===========================================================================
// helpers
// ===========================================================================
__device__ __forceinline__ void ldsm4(uint32_t* r, const void* p) {
    uint32_t a = (uint32_t)__cvta_generic_to_shared(p);
    asm volatile("ldmatrix.sync.aligned.m8n8.x4.shared.b16 {%0,%1,%2,%3}, [%4];"
                 : "=r"(r[0]), "=r"(r[1]), "=r"(r[2]), "=r"(r[3]) : "r"(a));
}
__device__ __forceinline__ void ldsm4t(uint32_t* r, const void* p) {
    uint32_t a = (uint32_t)__cvta_generic_to_shared(p);
    asm volatile("ldmatrix.sync.aligned.m8n8.x4.trans.shared.b16 {%0,%1,%2,%3}, [%4];"
                 : "=r"(r[0]), "=r"(r[1]), "=r"(r[2]), "=r"(r[3]) : "r"(a));
}
__device__ __forceinline__ void mma16816(float* c, const uint32_t* a, const uint32_t* b) {
    asm volatile("mma.sync.aligned.m16n8k16.row.col.f32.f16.f16.f32 "
                 "{%0,%1,%2,%3}, {%4,%5,%6,%7}, {%8,%9}, {%0,%1,%2,%3};"
                 : "+f"(c[0]), "+f"(c[1]), "+f"(c[2]), "+f"(c[3])
                 : "r"(a[0]), "r"(a[1]), "r"(a[2]), "r"(a[3]), "r"(b[0]), "r"(b[1]));
}
__device__ __forceinline__ uint32_t packh2(float a, float b) {
    __half2 h = __floats2half2_rn(a, b);
    return *reinterpret_cast<uint32_t*>(&h);
}

// ===========================================================================
// cvt / cvtw
// ===========================================================================
__global__ __launch_bounds__(256) void cvt_kernel(
    const float* __restrict__ in, __half* __restrict__ h, int n)
{
    int i = (blockIdx.x * 256 + threadIdx.x) * 8;
    if (i >= n) return;
    float4 v0 = *(const float4*)(in + i);
    float4 v1 = *(const float4*)(in + i + 4);
    *reinterpret_cast<__half2*>(h + i)     = __floats2half2_rn(v0.x, v0.y);
    *reinterpret_cast<__half2*>(h + i + 2) = __floats2half2_rn(v0.z, v0.w);
    *reinterpret_cast<__half2*>(h + i + 4) = __floats2half2_rn(v1.x, v1.y);
    *reinterpret_cast<__half2*>(h + i + 6) = __floats2half2_rn(v1.z, v1.w);
}

__global__ __launch_bounds__(256) void cvtw_kernel(
    const float* __restrict__ W, __half* __restrict__ h,
    int N, int Ntot, int off, int total)
{
    int i = (blockIdx.x * 256 + threadIdx.x) * 4;
    if (i >= total) return;
    int k = i / N, n = i - k * N;
    size_t o = (size_t)k * Ntot + off + n;
    float4 v = *(const float4*)(W + i);
    *reinterpret_cast<__half2*>(h + o)     = __floats2half2_rn(v.x, v.y);
    *reinterpret_cast<__half2*>(h + o + 2) = __floats2half2_rn(v.z, v.w);
}

// ===========================================================================
// GEMM (R8 config). EPI: 0 fp32; 1 +bias fp32; 2 fp16; 3 +bias+relu fp16
// ===========================================================================
#define ASTR 24
#define BSTR 136

template <int EPI>
__global__ __launch_bounds__(256) void tgemm(
    const __half* __restrict__ A, const __half* __restrict__ B,
    const float* __restrict__ bias, float* __restrict__ C,
    __half* __restrict__ Ch,
    int M, int N, int K)
{
    __shared__ __align__(16) __half sA[2][128 * ASTR];
    __shared__ __align__(16) __half sB[2][16 * BSTR];

    const int tid  = threadIdx.x;
    const int lane = tid & 31;
    const int w    = tid >> 5;
    const int wm   = w & 3;
    const int wn   = w >> 2;
    const int bm   = blockIdx.y * 128;
    const int bn   = blockIdx.x * 128;

    const int ar  = tid >> 1;
    const int acg = (tid & 1) * 8;
    const int br  = tid >> 4;
    const int bc  = (tid & 15) * 8;

    const __half* gA = A + (size_t)(bm + ar) * K + acg;
    const __half* gB = B + (size_t)br * N + bn + bc;

    int a_off[2];
#pragma unroll
    for (int mi = 0; mi < 2; mi++) {
        int row = wm * 32 + mi * 16 + (lane & 15);
        int col = (lane >> 4) * 8;
        a_off[mi] = row * ASTR + col;
    }
    int b_off[4];
    {
        int krow = lane & 15;
#pragma unroll
        for (int p = 0; p < 4; p++) {
            int col = wn * 64 + (p * 2 + (lane >> 4)) * 8;
            b_off[p] = krow * BSTR + col;
        }
    }

    float c[2][8][4];
#pragma unroll
    for (int mi = 0; mi < 2; mi++)
#pragma unroll
        for (int ni = 0; ni < 8; ni++)
#pragma unroll
            for (int e = 0; e < 4; e++) c[mi][ni][e] = 0.f;

    {
        uint4 va = *(const uint4*)gA;
        uint4 vb = *(const uint4*)gB;
        *(uint4*)&sA[0][ar * ASTR + acg] = va;
        *(uint4*)&sB[0][br * BSTR + bc]  = vb;
    }
    __syncthreads();

    const int nk = K >> 4;
    uint4 pa, pb;
    for (int kt = 0; kt < nk; kt++) {
        const int buf = kt & 1;
        if (kt + 1 < nk) {
            int k0 = (kt + 1) * 16;
            pa = *(const uint4*)(gA + k0);
            pb = *(const uint4*)(gB + (size_t)k0 * N);
        }

        uint32_t fa[2][4], fb[8][2];
#pragma unroll
        for (int mi = 0; mi < 2; mi++) ldsm4(fa[mi], &sA[buf][a_off[mi]]);
#pragma unroll
        for (int p = 0; p < 4; p++) {
            uint32_t r[4];
            ldsm4t(r, &sB[buf][b_off[p]]);
            fb[p * 2][0] = r[0]; fb[p * 2][1] = r[1];
            fb[p * 2 + 1][0] = r[2]; fb[p * 2 + 1][1] = r[3];
        }

#pragma unroll
        for (int mi = 0; mi < 2; mi++)
#pragma unroll
            for (int ni = 0; ni < 8; ni++) mma16816(c[mi][ni], fa[mi], fb[ni]);

        if (kt + 1 < nk) {
            const int nb = buf ^ 1;
            *(uint4*)&sA[nb][ar * ASTR + acg] = pa;
            *(uint4*)&sB[nb][br * BSTR + bc]  = pb;
            __syncthreads();
        }
    }

    const int er = lane >> 2;
    const int ec = (lane & 3) * 2;
#pragma unroll
    for (int mi = 0; mi < 2; mi++) {
#pragma unroll
        for (int ni = 0; ni < 8; ni++) {
            int r0 = bm + wm * 32 + mi * 16 + er;
            int cc = bn + wn * 64 + ni * 8 + ec;
            float v0 = c[mi][ni][0], v1 = c[mi][ni][1];
            float v2 = c[mi][ni][2], v3 = c[mi][ni][3];
            if (EPI == 1 || EPI == 3) {
                float bi0 = bias[cc], bi1 = bias[cc + 1];
                v0 += bi0; v1 += bi1; v2 += bi0; v3 += bi1;
            }
            if (EPI == 3) {
                v0 = fmaxf(v0, 0.f); v1 = fmaxf(v1, 0.f);
                v2 = fmaxf(v2, 0.f); v3 = fmaxf(v3, 0.f);
            }
            if (EPI == 2 || EPI == 3) {
                *reinterpret_cast<__half2*>(&Ch[(size_t)r0 * N + cc]) =
                    __floats2half2_rn(v0, v1);
                *reinterpret_cast<__half2*>(&Ch[(size_t)(r0 + 8) * N + cc]) =
                    __floats2half2_rn(v2, v3);
            } else {
                *(float2*)&C[(size_t)r0 * N + cc]       = make_float2(v0, v1);
                *(float2*)&C[(size_t)(r0 + 8) * N + cc] = make_float2(v2, v3);
            }
        }
    }
}

// ===========================================================================
// Tensor-core attention. Block = (b, h, 64-row q-tile); 8 warps (4 wm x 2 wn).
// Warp computes S rows 16wm..+15, cols 256wn..+255, S kept in registers.
// smem (halfs): sQ 64x72 | sKV 512x72 ; (floats) sMax 2x64 | sSum 2x64 | sO 64x68
// ===========================================================================
#define FA_SMEM 101376

__global__ __launch_bounds__(256) void fattn_kernel(
    const __half* __restrict__ QKV, __half* __restrict__ Oh)
{
    extern __shared__ __half sm16[];
    __half* sQ  = sm16;                       // 64*72
    __half* sKV = sm16 + 64 * 72;             // 512*72
    float*  sMax = (float*)(sm16 + 64 * 72 + 512 * 72);  // 2*64
    float*  sSum = sMax + 128;                           // 2*64
    float*  sO   = sSum + 128;                           // 64*68

    const int qt = blockIdx.x, h = blockIdx.y, b = blockIdx.z;
    const int tid = threadIdx.x, lane = tid & 31, w = tid >> 5;
    const int wm = w & 3, wn = w >> 2;
    const size_t rowbase = (size_t)b * SEQ;

    // load Q (64 x 64) and K (512 x 64), stride-72 rows
    for (int i = tid; i < 512; i += 256) {
        int r = i >> 3, cc = (i & 7) * 8;
        *(uint4*)&sQ[r * 72 + cc] =
            *(const uint4*)&QKV[(rowbase + qt * 64 + r) * QKVN + h * 64 + cc];
    }
    for (int i = tid; i < 4096; i += 256) {
        int r = i >> 3, cc = (i & 7) * 8;
        *(uint4*)&sKV[r * 72 + cc] =
            *(const uint4*)&QKV[(rowbase + r) * QKVN + 768 + h * 64 + cc];
    }
    __syncthreads();

    // ---- S = Q K^T (raw, scale applied in exp) ----
    float c[32][4];
#pragma unroll
    for (int t = 0; t < 32; t++)
#pragma unroll
        for (int e = 0; e < 4; e++) c[t][e] = 0.f;

    const int qrow   = 16 * wm + (lane & 15);
    const int bn_row = (lane & 7) + ((lane >> 4) & 1) * 8;
    const int bk_off = ((lane >> 3) & 1) * 8;

#pragma unroll
    for (int kt = 0; kt < 4; kt++) {
        uint32_t fa[4];
        ldsm4(fa, &sQ[qrow * 72 + kt * 16 + (lane >> 4) * 8]);
#pragma unroll
        for (int ng = 0; ng < 16; ng++) {
            int n0 = 256 * wn + ng * 16;
            uint32_t fb[4];
            ldsm4(fb, &sKV[(n0 + bn_row) * 72 + kt * 16 + bk_off]);
            mma16816(c[ng * 2],     fa, fb);
            mma16816(c[ng * 2 + 1], fa, fb + 2);
        }
    }

    // ---- row max (over this warp's 256 cols) ----
    float mx0 = -1e30f, mx1 = -1e30f;
#pragma unroll
    for (int t = 0; t < 32; t++) {
        mx0 = fmaxf(mx0, fmaxf(c[t][0], c[t][1]));
        mx1 = fmaxf(mx1, fmaxf(c[t][2], c[t][3]));
    }
    mx0 = fmaxf(mx0, __shfl_xor_sync(0xffffffffu, mx0, 1));
    mx0 = fmaxf(mx0, __shfl_xor_sync(0xffffffffu, mx0, 2));
    mx1 = fmaxf(mx1, __shfl_xor_sync(0xffffffffu, mx1, 1));
    mx1 = fmaxf(mx1, __shfl_xor_sync(0xffffffffu, mx1, 2));
    const int r_lo = 16 * wm + (lane >> 2);
    const int r_hi = r_lo + 8;
    if ((lane & 3) == 0) {
        sMax[wn * 64 + r_lo] = mx0;
        sMax[wn * 64 + r_hi] = mx1;
    }
    __syncthreads();   // all mma reads of sKV done; sMax visible
    const float m0 = fmaxf(sMax[r_lo], sMax[64 + r_lo]);
    const float m1 = fmaxf(sMax[r_hi], sMax[64 + r_hi]);

    // ---- load V into sKV (overlaps with exp below) ----
    for (int i = tid; i < 4096; i += 256) {
        int r = i >> 3, cc = (i & 7) * 8;
        *(uint4*)&sKV[r * 72 + cc] =
            *(const uint4*)&QKV[(rowbase + r) * QKVN + 1536 + h * 64 + cc];
    }

    // ---- exp + row sums ----
    const float sc = 0.125f;
    float s0 = 0.f, s1 = 0.f;
#pragma unroll
    for (int t = 0; t < 32; t++) {
        c[t][0] = __expf(sc * (c[t][0] - m0));
        c[t][1] = __expf(sc * (c[t][1] - m0));
        c[t][2] = __expf(sc * (c[t][2] - m1));
        c[t][3] = __expf(sc * (c[t][3] - m1));
        s0 += c[t][0] + c[t][1];
        s1 += c[t][2] + c[t][3];
    }
    s0 += __shfl_xor_sync(0xffffffffu, s0, 1);
    s0 += __shfl_xor_sync(0xffffffffu, s0, 2);
    s1 += __shfl_xor_sync(0xffffffffu, s1, 1);
    s1 += __shfl_xor_sync(0xffffffffu, s1, 2);
    if ((lane & 3) == 0) {
        sSum[wn * 64 + r_lo] = s0;
        sSum[wn * 64 + r_hi] = s1;
    }
    __syncthreads();   // sums visible AND V store complete
    const float inv0 = 1.0f / (sSum[r_lo] + sSum[64 + r_lo]);
    const float inv1 = 1.0f / (sSum[r_hi] + sSum[64 + r_hi]);

    // ---- convert P (register S tiles) into fp16 A-fragments ----
    uint32_t af[16][4];
#pragma unroll
    for (int ks = 0; ks < 16; ks++) {
        af[ks][0] = packh2(c[2 * ks][0],     c[2 * ks][1]);
        af[ks][1] = packh2(c[2 * ks][2],     c[2 * ks][3]);
        af[ks][2] = packh2(c[2 * ks + 1][0], c[2 * ks + 1][1]);
        af[ks][3] = packh2(c[2 * ks + 1][2], c[2 * ks + 1][3]);
    }

    // ---- O_partial = P_half @ V_half ----
    float o[8][4];
#pragma unroll
    for (int nt = 0; nt < 8; nt++)
#pragma unroll
        for (int e = 0; e < 4; e++) o[nt][e] = 0.f;

    const int vk = lane & 15;
#pragma unroll
    for (int ks = 0; ks < 16; ks++) {
        const int k0 = 256 * wn + ks * 16;
#pragma unroll
        for (int p = 0; p < 4; p++) {
            uint32_t r4[4];
            ldsm4t(r4, &sKV[(k0 + vk) * 72 + (p * 2 + (lane >> 4)) * 8]);
            mma16816(o[p * 2],     af[ks], r4);
            mma16816(o[p * 2 + 1], af[ks], r4 + 2);
        }
    }

    // ---- combine wn halves, scale, write ----
    const int er = lane >> 2;
    const int ec = (lane & 3) * 2;
    if (wn == 1) {
#pragma unroll
        for (int nt = 0; nt < 8; nt++) {
            sO[(16 * wm + er) * 68 + nt * 8 + ec]         = o[nt][0];
            sO[(16 * wm + er) * 68 + nt * 8 + ec + 1]     = o[nt][1];
            sO[(16 * wm + er + 8) * 68 + nt * 8 + ec]     = o[nt][2];
            sO[(16 * wm + er + 8) * 68 + nt * 8 + ec + 1] = o[nt][3];
        }
    }
    __syncthreads();
    if (wn == 0) {
        const size_t out_lo = (rowbase + qt * 64 + r_lo) * EMB + h * 64;
        const size_t out_hi = (rowbase + qt * 64 + r_hi) * EMB + h * 64;
#pragma unroll
        for (int nt = 0; nt < 8; nt++) {
            float v0 = (o[nt][0] + sO[r_lo * 68 + nt * 8 + ec])     * inv0;
            float v1 = (o[nt][1] + sO[r_lo * 68 + nt * 8 + ec + 1]) * inv0;
            float v2 = (o[nt][2] + sO[r_hi * 68 + nt * 8 + ec])     * inv1;
            float v3 = (o[nt][3] + sO[r_hi * 68 + nt * 8 + ec + 1]) * inv1;
            *reinterpret_cast<__half2*>(&Oh[out_lo + nt * 8 + ec]) =
                __floats2half2_rn(v0, v1);
            *reinterpret_cast<__half2*>(&Oh[out_hi + nt * 8 + ec]) =
                __floats2half2_rn(v2, v3);
        }
    }
}

// ===========================================================================
// Fused residual + LayerNorm (+ optional fp16 out)
// ===========================================================================
__global__ __launch_bounds__(256) void add_ln_kernel(
    const float* __restrict__ x, const float* __restrict__ r,
    const float* __restrict__ gamma, const float* __restrict__ beta,
    float* __restrict__ out, __half* __restrict__ oh)
{
    const int row = blockIdx.x;
    const int tid = threadIdx.x;
    const float* xr = x + (size_t)row * EMB;
    const float* rr = r + (size_t)row * EMB;

    float v[3];
    float s = 0.f;
#pragma unroll
    for (int i = 0; i < 3; i++) {
        int cx = tid + i * 256;
        float t = xr[cx] + rr[cx];
        v[i] = t;
        s += t;
    }

    __shared__ float red[8];
    const int wid = tid >> 5, lane = tid & 31;
#pragma unroll
    for (int o = 16; o > 0; o >>= 1) s += __shfl_xor_sync(0xffffffffu, s, o);
    if (lane == 0) red[wid] = s;
    __syncthreads();
    if (tid == 0) {
        float t = 0.f;
#pragma unroll
        for (int i = 0; i < 8; i++) t += red[i];
        red[0] = t;
    }
    __syncthreads();
    const float mean = red[0] * (1.0f / 768.0f);

    float s2 = 0.f;
#pragma unroll
    for (int i = 0; i < 3; i++) {
        float d = v[i] - mean;
        s2 += d * d;
    }
#pragma unroll
    for (int o = 16; o > 0; o >>= 1) s2 += __shfl_xor_sync(0xffffffffu, s2, o);
    __syncthreads();
    if (lane == 0) red[wid] = s2;
    __syncthreads();
    if (tid == 0) {
        float t = 0.f;
#pragma unroll
        for (int i = 0; i < 8; i++) t += red[i];
        red[0] = t;
    }
    __syncthreads();
    const float var  = red[0] * (1.0f / 768.0f);
    const float rstd = rsqrtf(var + 1e-5f);

#pragma unroll
    for (int i = 0; i < 3; i++) {
        int cx = tid + i * 256;
        float o = (v[i] - mean) * rstd * gamma[cx] + beta[cx];
        size_t idx = (size_t)row * EMB + cx;
        out[idx] = o;
        if (oh) oh[idx] = __float2half_rn(o);
    }
}

// ===========================================================================
// Launch
// ===========================================================================
extern "C" void kernel_launch(void* const* d_in, const int* in_sizes, int n_in,
                              void* d_out, int out_size)
{
    (void)in_sizes; (void)n_in; (void)out_size;

    const float* x   = (const float*)d_in[0];
    const float* Wq  = (const float*)d_in[1];
    const float* Wk  = (const float*)d_in[2];
    const float* Wv  = (const float*)d_in[3];
    const float* Wo  = (const float*)d_in[4];
    const float* W1  = (const float*)d_in[5];
    const float* b1  = (const float*)d_in[6];
    const float* W2  = (const float*)d_in[7];
    const float* b2  = (const float*)d_in[8];
    const float* g1  = (const float*)d_in[9];
    const float* be1 = (const float*)d_in[10];
    const float* g2  = (const float*)d_in[11];
    const float* be2 = (const float*)d_in[12];
    float* out = (float*)d_out;

    float *tmp, *x1;
    __half *qkv, *ah, *ch, *fh, *wh;
    cudaGetSymbolAddress((void**)&qkv, g_qkv);
    cudaGetSymbolAddress((void**)&tmp, g_tmp);
    cudaGetSymbolAddress((void**)&x1,  g_x1);
    cudaGetSymbolAddress((void**)&ah,  g_ah);
    cudaGetSymbolAddress((void**)&ch,  g_ch);
    cudaGetSymbolAddress((void**)&fh,  g_fh);
    cudaGetSymbolAddress((void**)&wh,  g_wh);

    cudaFuncSetAttribute(fattn_kernel,
                         cudaFuncAttributeMaxDynamicSharedMemorySize, FA_SMEM);

    const size_t EE = (size_t)EMB * EMB;
    const size_t EF = (size_t)EMB * FFND;
    const size_t OQKV = 0, OO_ = 3 * EE, O1_ = 4 * EE, O2_ = 4 * EE + EF;

    dim3 blk(256);

    // activation conversion (x)
    cvt_kernel<<<NTOK * EMB / 2048, blk>>>(x, ah, NTOK * EMB);
    // weight conversions; Wq/Wk/Wv scatter into merged [768,2304] buffer
    cvtw_kernel<<<(int)(EE / 1024), blk>>>(Wq, wh + OQKV, EMB, QKVN, 0,    (int)EE);
    cvtw_kernel<<<(int)(EE / 1024), blk>>>(Wk, wh + OQKV, EMB, QKVN, 768,  (int)EE);
    cvtw_kernel<<<(int)(EE / 1024), blk>>>(Wv, wh + OQKV, EMB, QKVN, 1536, (int)EE);
    cvtw_kernel<<<(int)(EE / 1024), blk>>>(Wo, wh + OO_,  EMB, EMB,  0,    (int)EE);
    cvtw_kernel<<<(int)(EF / 1024), blk>>>(W1, wh + O1_,  FFND, FFND, 0,   (int)EF);
    cvtw_kernel<<<(int)(EF / 1024), blk>>>(W2, wh + O2_,  EMB,  EMB,  0,   (int)EF);

    // fused QKV projection: [NTOK,768] @ [768,2304] -> fp16
    tgemm<2><<<dim3(QKVN / 128, NTOK / 128), blk>>>(
        ah, wh + OQKV, nullptr, nullptr, qkv, NTOK, QKVN, EMB);

    // tensor-core attention -> ctx (fp16)
    fattn_kernel<<<dim3(SEQ / 64, HEADS, BATCH), blk, FA_SMEM>>>(qkv, ch);

    // output projection (fp32 out for residual)
    tgemm<0><<<dim3(EMB / 128, NTOK / 128), blk>>>(
        ch, wh + OO_, nullptr, tmp, nullptr, NTOK, EMB, EMB);

    // residual + LN1 (emits x1 as fp16 into ah)
    add_ln_kernel<<<NTOK, blk>>>(x, tmp, g1, be1, x1, ah);

    // FFN
    tgemm<3><<<dim3(FFND / 128, NTOK / 128), blk>>>(
        ah, wh + O1_, b1, nullptr, fh, NTOK, FFND, EMB);
    tgemm<1><<<dim3(EMB / 128, NTOK / 128), blk>>>(
        fh, wh + O2_, b2, tmp, nullptr, NTOK, EMB, FFND);

    // residual + LN2
    add_ln_kernel<<<NTOK, blk>>>(x1, tmp, g2, be2, out, nullptr);
}

// round 15
// speedup vs baseline: 1.7181x; 1.0152x over previous
#include <cuda_runtime.h>
#include <cuda_fp16.h>
#include <cstdint>

// ---------------------------------------------------------------------------
// ViT encoder block. GEMMs: single-pass fp16 mma.sync, 128x128 CTA tile,
// 32x64 warp tile; mainloop order ldmatrix->STS->LDG->MMA->bar.
// Residual branch fp16. Tensor-core attention (S in registers).
// ---------------------------------------------------------------------------

#define NTOK   16384
#define EMB    768
#define FFND   3072
#define HEADS  12
#define DK     64
#define SEQ    512
#define BATCH  32
#define QKVN   2304

// ----- fp32 scratch -----
__device__ __align__(128) float g_x1 [NTOK * EMB];

// ----- fp16 scratch -----
__device__ __align__(128) __half g_qkv[NTOK * QKVN];  // QKV; later reused as fp16 tmp
__device__ __align__(128) __half g_ah[NTOK * EMB];
__device__ __align__(128) __half g_ch[NTOK * EMB];
__device__ __align__(128) __half g_fh[NTOK * FFND];
#define WTOT 7077888
__device__ __align__(128) __half g_wh[WTOT];

// ===========================================================================
// helpers
// ===========================================================================
__device__ __forceinline__ void ldsm4(uint32_t* r, const void* p) {
    uint32_t a = (uint32_t)__cvta_generic_to_shared(p);
    asm volatile("ldmatrix.sync.aligned.m8n8.x4.shared.b16 {%0,%1,%2,%3}, [%4];"
                 : "=r"(r[0]), "=r"(r[1]), "=r"(r[2]), "=r"(r[3]) : "r"(a));
}
__device__ __forceinline__ void ldsm4t(uint32_t* r, const void* p) {
    uint32_t a = (uint32_t)__cvta_generic_to_shared(p);
    asm volatile("ldmatrix.sync.aligned.m8n8.x4.trans.shared.b16 {%0,%1,%2,%3}, [%4];"
                 : "=r"(r[0]), "=r"(r[1]), "=r"(r[2]), "=r"(r[3]) : "r"(a));
}
__device__ __forceinline__ void mma16816(float* c, const uint32_t* a, const uint32_t* b) {
    asm volatile("mma.sync.aligned.m16n8k16.row.col.f32.f16.f16.f32 "
                 "{%0,%1,%2,%3}, {%4,%5,%6,%7}, {%8,%9}, {%0,%1,%2,%3};"
                 : "+f"(c[0]), "+f"(c[1]), "+f"(c[2]), "+f"(c[3])
                 : "r"(a[0]), "r"(a[1]), "r"(a[2]), "r"(a[3]), "r"(b[0]), "r"(b[1]));
}
__device__ __forceinline__ uint32_t packh2(float a, float b) {
    __half2 h = __floats2half2_rn(a, b);
    return *reinterpret_cast<uint32_t*>(&h);
}

// ===========================================================================
// cvt / cvtw
// ===========================================================================
__global__ __launch_bounds__(256) void cvt_kernel(
    const float* __restrict__ in, __half* __restrict__ h, int n)
{
    int i = (blockIdx.x * 256 + threadIdx.x) * 8;
    if (i >= n) return;
    float4 v0 = *(const float4*)(in + i);
    float4 v1 = *(const float4*)(in + i + 4);
    *reinterpret_cast<__half2*>(h + i)     = __floats2half2_rn(v0.x, v0.y);
    *reinterpret_cast<__half2*>(h + i + 2) = __floats2half2_rn(v0.z, v0.w);
    *reinterpret_cast<__half2*>(h + i + 4) = __floats2half2_rn(v1.x, v1.y);
    *reinterpret_cast<__half2*>(h + i + 6) = __floats2half2_rn(v1.z, v1.w);
}

__global__ __launch_bounds__(256) void cvtw_kernel(
    const float* __restrict__ W, __half* __restrict__ h,
    int N, int Ntot, int off, int total)
{
    int i = (blockIdx.x * 256 + threadIdx.x) * 4;
    if (i >= total) return;
    int k = i / N, n = i - k * N;
    size_t o = (size_t)k * Ntot + off + n;
    float4 v = *(const float4*)(W + i);
    *reinterpret_cast<__half2*>(h + o)     = __floats2half2_rn(v.x, v.y);
    *reinterpret_cast<__half2*>(h + o + 2) = __floats2half2_rn(v.z, v.w);
}

// ===========================================================================
// GEMM: all outputs fp16. EPI: 2 = plain; 3 = +bias+relu; 4 = +bias
// Mainloop: ldmatrix -> STS(prefetched) -> LDG(next) -> MMA -> bar
// ===========================================================================
#define ASTR 24
#define BSTR 136

template <int EPI>
__global__ __launch_bounds__(256) void tgemm(
    const __half* __restrict__ A, const __half* __restrict__ B,
    const float* __restrict__ bias, __half* __restrict__ Ch,
    int M, int N, int K)
{
    __shared__ __align__(16) __half sA[2][128 * ASTR];
    __shared__ __align__(16) __half sB[2][16 * BSTR];

    const int tid  = threadIdx.x;
    const int lane = tid & 31;
    const int w    = tid >> 5;
    const int wm   = w & 3;
    const int wn   = w >> 2;
    const int bm   = blockIdx.y * 128;
    const int bn   = blockIdx.x * 128;

    const int ar  = tid >> 1;
    const int acg = (tid & 1) * 8;
    const int br  = tid >> 4;
    const int bc  = (tid & 15) * 8;

    const __half* gA = A + (size_t)(bm + ar) * K + acg;
    const __half* gB = B + (size_t)br * N + bn + bc;

    int a_off[2];
#pragma unroll
    for (int mi = 0; mi < 2; mi++) {
        int row = wm * 32 + mi * 16 + (lane & 15);
        int col = (lane >> 4) * 8;
        a_off[mi] = row * ASTR + col;
    }
    int b_off[4];
    {
        int krow = lane & 15;
#pragma unroll
        for (int p = 0; p < 4; p++) {
            int col = wn * 64 + (p * 2 + (lane >> 4)) * 8;
            b_off[p] = krow * BSTR + col;
        }
    }

    float c[2][8][4];
#pragma unroll
    for (int mi = 0; mi < 2; mi++)
#pragma unroll
        for (int ni = 0; ni < 8; ni++)
#pragma unroll
            for (int e = 0; e < 4; e++) c[mi][ni][e] = 0.f;

    const int nk = K >> 4;

    // prologue: tile 0 -> buf 0; prefetch tile 1 into regs
    uint4 pa, pb;
    {
        uint4 va = *(const uint4*)gA;
        uint4 vb = *(const uint4*)gB;
        *(uint4*)&sA[0][ar * ASTR + acg] = va;
        *(uint4*)&sB[0][br * BSTR + bc]  = vb;
    }
    if (nk > 1) {
        pa = *(const uint4*)(gA + 16);
        pb = *(const uint4*)(gB + (size_t)16 * N);
    }
    __syncthreads();

    for (int kt = 0; kt < nk; kt++) {
        const int buf = kt & 1;

        uint32_t fa[2][4], fb[8][2];
#pragma unroll
        for (int mi = 0; mi < 2; mi++) ldsm4(fa[mi], &sA[buf][a_off[mi]]);
#pragma unroll
        for (int p = 0; p < 4; p++) {
            uint32_t r[4];
            ldsm4t(r, &sB[buf][b_off[p]]);
            fb[p * 2][0] = r[0]; fb[p * 2][1] = r[1];
            fb[p * 2 + 1][0] = r[2]; fb[p * 2 + 1][1] = r[3];
        }

        // store prefetched tile kt+1 into buf^1 BEFORE the MMA block, then
        // immediately issue the LDG for tile kt+2 (full-iteration slack).
        if (kt + 1 < nk) {
            const int nb = buf ^ 1;
            *(uint4*)&sA[nb][ar * ASTR + acg] = pa;
            *(uint4*)&sB[nb][br * BSTR + bc]  = pb;
        }
        if (kt + 2 < nk) {
            int k0 = (kt + 2) * 16;
            pa = *(const uint4*)(gA + k0);
            pb = *(const uint4*)(gB + (size_t)k0 * N);
        }

#pragma unroll
        for (int mi = 0; mi < 2; mi++)
#pragma unroll
            for (int ni = 0; ni < 8; ni++) mma16816(c[mi][ni], fa[mi], fb[ni]);

        if (kt + 1 < nk) __syncthreads();
    }

    // epilogue (all fp16)
    const int er = lane >> 2;
    const int ec = (lane & 3) * 2;
#pragma unroll
    for (int mi = 0; mi < 2; mi++) {
#pragma unroll
        for (int ni = 0; ni < 8; ni++) {
            int r0 = bm + wm * 32 + mi * 16 + er;
            int cc = bn + wn * 64 + ni * 8 + ec;
            float v0 = c[mi][ni][0], v1 = c[mi][ni][1];
            float v2 = c[mi][ni][2], v3 = c[mi][ni][3];
            if (EPI >= 3) {
                float bi0 = bias[cc], bi1 = bias[cc + 1];
                v0 += bi0; v1 += bi1; v2 += bi0; v3 += bi1;
            }
            if (EPI == 3) {
                v0 = fmaxf(v0, 0.f); v1 = fmaxf(v1, 0.f);
                v2 = fmaxf(v2, 0.f); v3 = fmaxf(v3, 0.f);
            }
            *reinterpret_cast<__half2*>(&Ch[(size_t)r0 * N + cc]) =
                __floats2half2_rn(v0, v1);
            *reinterpret_cast<__half2*>(&Ch[(size_t)(r0 + 8) * N + cc]) =
                __floats2half2_rn(v2, v3);
        }
    }
}

// ===========================================================================
// Tensor-core attention (unchanged from R13).
// ===========================================================================
#define FA_SMEM 101376

__global__ __launch_bounds__(256) void fattn_kernel(
    const __half* __restrict__ QKV, __half* __restrict__ Oh)
{
    extern __shared__ __half sm16[];
    __half* sQ  = sm16;
    __half* sKV = sm16 + 64 * 72;
    float*  sMax = (float*)(sm16 + 64 * 72 + 512 * 72);
    float*  sSum = sMax + 128;
    float*  sO   = sSum + 128;

    const int qt = blockIdx.x, h = blockIdx.y, b = blockIdx.z;
    const int tid = threadIdx.x, lane = tid & 31, w = tid >> 5;
    const int wm = w & 3, wn = w >> 2;
    const size_t rowbase = (size_t)b * SEQ;

    for (int i = tid; i < 512; i += 256) {
        int r = i >> 3, cc = (i & 7) * 8;
        *(uint4*)&sQ[r * 72 + cc] =
            *(const uint4*)&QKV[(rowbase + qt * 64 + r) * QKVN + h * 64 + cc];
    }
    for (int i = tid; i < 4096; i += 256) {
        int r = i >> 3, cc = (i & 7) * 8;
        *(uint4*)&sKV[r * 72 + cc] =
            *(const uint4*)&QKV[(rowbase + r) * QKVN + 768 + h * 64 + cc];
    }
    __syncthreads();

    float c[32][4];
#pragma unroll
    for (int t = 0; t < 32; t++)
#pragma unroll
        for (int e = 0; e < 4; e++) c[t][e] = 0.f;

    const int qrow   = 16 * wm + (lane & 15);
    const int bn_row = (lane & 7) + ((lane >> 4) & 1) * 8;
    const int bk_off = ((lane >> 3) & 1) * 8;

#pragma unroll
    for (int kt = 0; kt < 4; kt++) {
        uint32_t fa[4];
        ldsm4(fa, &sQ[qrow * 72 + kt * 16 + (lane >> 4) * 8]);
#pragma unroll
        for (int ng = 0; ng < 16; ng++) {
            int n0 = 256 * wn + ng * 16;
            uint32_t fb[4];
            ldsm4(fb, &sKV[(n0 + bn_row) * 72 + kt * 16 + bk_off]);
            mma16816(c[ng * 2],     fa, fb);
            mma16816(c[ng * 2 + 1], fa, fb + 2);
        }
    }

    float mx0 = -1e30f, mx1 = -1e30f;
#pragma unroll
    for (int t = 0; t < 32; t++) {
        mx0 = fmaxf(mx0, fmaxf(c[t][0], c[t][1]));
        mx1 = fmaxf(mx1, fmaxf(c[t][2], c[t][3]));
    }
    mx0 = fmaxf(mx0, __shfl_xor_sync(0xffffffffu, mx0, 1));
    mx0 = fmaxf(mx0, __shfl_xor_sync(0xffffffffu, mx0, 2));
    mx1 = fmaxf(mx1, __shfl_xor_sync(0xffffffffu, mx1, 1));
    mx1 = fmaxf(mx1, __shfl_xor_sync(0xffffffffu, mx1, 2));
    const int r_lo = 16 * wm + (lane >> 2);
    const int r_hi = r_lo + 8;
    if ((lane & 3) == 0) {
        sMax[wn * 64 + r_lo] = mx0;
        sMax[wn * 64 + r_hi] = mx1;
    }
    __syncthreads();
    const float m0 = fmaxf(sMax[r_lo], sMax[64 + r_lo]);
    const float m1 = fmaxf(sMax[r_hi], sMax[64 + r_hi]);

    for (int i = tid; i < 4096; i += 256) {
        int r = i >> 3, cc = (i & 7) * 8;
        *(uint4*)&sKV[r * 72 + cc] =
            *(const uint4*)&QKV[(rowbase + r) * QKVN + 1536 + h * 64 + cc];
    }

    const float sc = 0.125f;
    float s0 = 0.f, s1 = 0.f;
#pragma unroll
    for (int t = 0; t < 32; t++) {
        c[t][0] = __expf(sc * (c[t][0] - m0));
        c[t][1] = __expf(sc * (c[t][1] - m0));
        c[t][2] = __expf(sc * (c[t][2] - m1));
        c[t][3] = __expf(sc * (c[t][3] - m1));
        s0 += c[t][0] + c[t][1];
        s1 += c[t][2] + c[t][3];
    }
    s0 += __shfl_xor_sync(0xffffffffu, s0, 1);
    s0 += __shfl_xor_sync(0xffffffffu, s0, 2);
    s1 += __shfl_xor_sync(0xffffffffu, s1, 1);
    s1 += __shfl_xor_sync(0xffffffffu, s1, 2);
    if ((lane & 3) == 0) {
        sSum[wn * 64 + r_lo] = s0;
        sSum[wn * 64 + r_hi] = s1;
    }
    __syncthreads();
    const float inv0 = 1.0f / (sSum[r_lo] + sSum[64 + r_lo]);
    const float inv1 = 1.0f / (sSum[r_hi] + sSum[64 + r_hi]);

    uint32_t af[16][4];
#pragma unroll
    for (int ks = 0; ks < 16; ks++) {
        af[ks][0] = packh2(c[2 * ks][0],     c[2 * ks][1]);
        af[ks][1] = packh2(c[2 * ks][2],     c[2 * ks][3]);
        af[ks][2] = packh2(c[2 * ks + 1][0], c[2 * ks + 1][1]);
        af[ks][3] = packh2(c[2 * ks + 1][2], c[2 * ks + 1][3]);
    }

    float o[8][4];
#pragma unroll
    for (int nt = 0; nt < 8; nt++)
#pragma unroll
        for (int e = 0; e < 4; e++) o[nt][e] = 0.f;

    const int vk = lane & 15;
#pragma unroll
    for (int ks = 0; ks < 16; ks++) {
        const int k0 = 256 * wn + ks * 16;
#pragma unroll
        for (int p = 0; p < 4; p++) {
            uint32_t r4[4];
            ldsm4t(r4, &sKV[(k0 + vk) * 72 + (p * 2 + (lane >> 4)) * 8]);
            mma16816(o[p * 2],     af[ks], r4);
            mma16816(o[p * 2 + 1], af[ks], r4 + 2);
        }
    }

    const int er = lane >> 2;
    const int ec = (lane & 3) * 2;
    if (wn == 1) {
#pragma unroll
        for (int nt = 0; nt < 8; nt++) {
            sO[(16 * wm + er) * 68 + nt * 8 + ec]         = o[nt][0];
            sO[(16 * wm + er) * 68 + nt * 8 + ec + 1]     = o[nt][1];
            sO[(16 * wm + er + 8) * 68 + nt * 8 + ec]     = o[nt][2];
            sO[(16 * wm + er + 8) * 68 + nt * 8 + ec + 1] = o[nt][3];
        }
    }
    __syncthreads();
    if (wn == 0) {
        const size_t out_lo = (rowbase + qt * 64 + r_lo) * EMB + h * 64;
        const size_t out_hi = (rowbase + qt * 64 + r_hi) * EMB + h * 64;
#pragma unroll
        for (int nt = 0; nt < 8; nt++) {
            float v0 = (o[nt][0] + sO[r_lo * 68 + nt * 8 + ec])     * inv0;
            float v1 = (o[nt][1] + sO[r_lo * 68 + nt * 8 + ec + 1]) * inv0;
            float v2 = (o[nt][2] + sO[r_hi * 68 + nt * 8 + ec])     * inv1;
            float v3 = (o[nt][3] + sO[r_hi * 68 + nt * 8 + ec + 1]) * inv1;
            *reinterpret_cast<__half2*>(&Oh[out_lo + nt * 8 + ec]) =
                __floats2half2_rn(v0, v1);
            *reinterpret_cast<__half2*>(&Oh[out_hi + nt * 8 + ec]) =
                __floats2half2_rn(v2, v3);
        }
    }
}

// ===========================================================================
// Fused residual + LayerNorm; residual branch is fp16.
// ===========================================================================
__global__ __launch_bounds__(256) void add_ln_kernel(
    const float* __restrict__ x, const __half* __restrict__ r,
    const float* __restrict__ gamma, const float* __restrict__ beta,
    float* __restrict__ out, __half* __restrict__ oh)
{
    const int row = blockIdx.x;
    const int tid = threadIdx.x;
    const float* xr = x + (size_t)row * EMB;
    const __half* rr = r + (size_t)row * EMB;

    float v[3];
    float s = 0.f;
#pragma unroll
    for (int i = 0; i < 3; i++) {
        int cx = tid + i * 256;
        float t = xr[cx] + __half2float(rr[cx]);
        v[i] = t;
        s += t;
    }

    __shared__ float red[8];
    const int wid = tid >> 5, lane = tid & 31;
#pragma unroll
    for (int o = 16; o > 0; o >>= 1) s += __shfl_xor_sync(0xffffffffu, s, o);
    if (lane == 0) red[wid] = s;
    __syncthreads();
    if (tid == 0) {
        float t = 0.f;
#pragma unroll
        for (int i = 0; i < 8; i++) t += red[i];
        red[0] = t;
    }
    __syncthreads();
    const float mean = red[0] * (1.0f / 768.0f);

    float s2 = 0.f;
#pragma unroll
    for (int i = 0; i < 3; i++) {
        float d = v[i] - mean;
        s2 += d * d;
    }
#pragma unroll
    for (int o = 16; o > 0; o >>= 1) s2 += __shfl_xor_sync(0xffffffffu, s2, o);
    __syncthreads();
    if (lane == 0) red[wid] = s2;
    __syncthreads();
    if (tid == 0) {
        float t = 0.f;
#pragma unroll
        for (int i = 0; i < 8; i++) t += red[i];
        red[0] = t;
    }
    __syncthreads();
    const float var  = red[0] * (1.0f / 768.0f);
    const float rstd = rsqrtf(var + 1e-5f);

#pragma unroll
    for (int i = 0; i < 3; i++) {
        int cx = tid + i * 256;
        float o = (v[i] - mean) * rstd * gamma[cx] + beta[cx];
        size_t idx = (size_t)row * EMB + cx;
        out[idx] = o;
        if (oh) oh[idx] = __float2half_rn(o);
    }
}

// ===========================================================================
// Launch
// ===========================================================================
extern "C" void kernel_launch(void* const* d_in, const int* in_sizes, int n_in,
                              void* d_out, int out_size)
{
    (void)in_sizes; (void)n_in; (void)out_size;

    const float* x   = (const float*)d_in[0];
    const float* Wq  = (const float*)d_in[1];
    const float* Wk  = (const float*)d_in[2];
    const float* Wv  = (const float*)d_in[3];
    const float* Wo  = (const float*)d_in[4];
    const float* W1  = (const float*)d_in[5];
    const float* b1  = (const float*)d_in[6];
    const float* W2  = (const float*)d_in[7];
    const float* b2  = (const float*)d_in[8];
    const float* g1  = (const float*)d_in[9];
    const float* be1 = (const float*)d_in[10];
    const float* g2  = (const float*)d_in[11];
    const float* be2 = (const float*)d_in[12];
    float* out = (float*)d_out;

    float *x1;
    __half *qkv, *ah, *ch, *fh, *wh;
    cudaGetSymbolAddress((void**)&qkv, g_qkv);
    cudaGetSymbolAddress((void**)&x1,  g_x1);
    cudaGetSymbolAddress((void**)&ah,  g_ah);
    cudaGetSymbolAddress((void**)&ch,  g_ch);
    cudaGetSymbolAddress((void**)&fh,  g_fh);
    cudaGetSymbolAddress((void**)&wh,  g_wh);
    __half* tmp16 = qkv;   // g_qkv is free after attention

    cudaFuncSetAttribute(fattn_kernel,
                         cudaFuncAttributeMaxDynamicSharedMemorySize, FA_SMEM);

    const size_t EE = (size_t)EMB * EMB;
    const size_t EF = (size_t)EMB * FFND;
    const size_t OQKV = 0, OO_ = 3 * EE, O1_ = 4 * EE, O2_ = 4 * EE + EF;

    dim3 blk(256);

    cvt_kernel<<<NTOK * EMB / 2048, blk>>>(x, ah, NTOK * EMB);
    cvtw_kernel<<<(int)(EE / 1024), blk>>>(Wq, wh + OQKV, EMB, QKVN, 0,    (int)EE);
    cvtw_kernel<<<(int)(EE / 1024), blk>>>(Wk, wh + OQKV, EMB, QKVN, 768,  (int)EE);
    cvtw_kernel<<<(int)(EE / 1024), blk>>>(Wv, wh + OQKV, EMB, QKVN, 1536, (int)EE);
    cvtw_kernel<<<(int)(EE / 1024), blk>>>(Wo, wh + OO_,  EMB, EMB,  0,    (int)EE);
    cvtw_kernel<<<(int)(EF / 1024), blk>>>(W1, wh + O1_,  FFND, FFND, 0,   (int)EF);
    cvtw_kernel<<<(int)(EF / 1024), blk>>>(W2, wh + O2_,  EMB,  EMB,  0,   (int)EF);

    // fused QKV projection -> fp16
    tgemm<2><<<dim3(QKVN / 128, NTOK / 128), blk>>>(
        ah, wh + OQKV, nullptr, qkv, NTOK, QKVN, EMB);

    // tensor-core attention -> ctx (fp16)
    fattn_kernel<<<dim3(SEQ / 64, HEADS, BATCH), blk, FA_SMEM>>>(qkv, ch);

    // output projection -> fp16 tmp (reuses qkv buffer)
    tgemm<2><<<dim3(EMB / 128, NTOK / 128), blk>>>(
        ch, wh + OO_, nullptr, tmp16, NTOK, EMB, EMB);

    // residual + LN1 (emits x1 fp32 + fp16 into ah)
    add_ln_kernel<<<NTOK, blk>>>(x, tmp16, g1, be1, x1, ah);

    // FFN
    tgemm<3><<<dim3(FFND / 128, NTOK / 128), blk>>>(
        ah, wh + O1_, b1, fh, NTOK, FFND, EMB);
    tgemm<4><<<dim3(EMB / 128, NTOK / 128), blk>>>(
        fh, wh + O2_, b2, tmp16, NTOK, EMB, FFND);

    // residual + LN2
    add_ln_kernel<<<NTOK, blk>>>(x1, tmp16, g2, be2, out, nullptr);
}

// round 16
// speedup vs baseline: 1.7250x; 1.0040x over previous
#include <cuda_runtime.h>
#include <cuda_fp16.h>
#include <cstdint>

// ---------------------------------------------------------------------------
// ViT encoder block. GEMMs: single-pass fp16 mma.sync, 128x128 CTA tile,
// 32x64 warp tile, __launch_bounds__(256,2). Residual branch fp16.
// Tensor-core attention (S in registers). Merged weight conversion.
// ---------------------------------------------------------------------------

#define NTOK   16384
#define EMB    768
#define FFND   3072
#define HEADS  12
#define DK     64
#define SEQ    512
#define BATCH  32
#define QKVN   2304

// ----- fp32 scratch -----
__device__ __align__(128) float g_x1 [NTOK * EMB];

// ----- fp16 scratch -----
__device__ __align__(128) __half g_qkv[NTOK * QKVN];  // QKV; later reused as fp16 tmp
__device__ __align__(128) __half g_ah[NTOK * EMB];
__device__ __align__(128) __half g_ch[NTOK * EMB];
__device__ __align__(128) __half g_fh[NTOK * FFND];
#define WTOT 7077888
__device__ __align__(128) __half g_wh[WTOT];

// ===========================================================================
// helpers
// ===========================================================================
__device__ __forceinline__ void ldsm4(uint32_t* r, const void* p) {
    uint32_t a = (uint32_t)__cvta_generic_to_shared(p);
    asm volatile("ldmatrix.sync.aligned.m8n8.x4.shared.b16 {%0,%1,%2,%3}, [%4];"
                 : "=r"(r[0]), "=r"(r[1]), "=r"(r[2]), "=r"(r[3]) : "r"(a));
}
__device__ __forceinline__ void ldsm4t(uint32_t* r, const void* p) {
    uint32_t a = (uint32_t)__cvta_generic_to_shared(p);
    asm volatile("ldmatrix.sync.aligned.m8n8.x4.trans.shared.b16 {%0,%1,%2,%3}, [%4];"
                 : "=r"(r[0]), "=r"(r[1]), "=r"(r[2]), "=r"(r[3]) : "r"(a));
}
__device__ __forceinline__ void mma16816(float* c, const uint32_t* a, const uint32_t* b) {
    asm volatile("mma.sync.aligned.m16n8k16.row.col.f32.f16.f16.f32 "
                 "{%0,%1,%2,%3}, {%4,%5,%6,%7}, {%8,%9}, {%0,%1,%2,%3};"
                 : "+f"(c[0]), "+f"(c[1]), "+f"(c[2]), "+f"(c[3])
                 : "r"(a[0]), "r"(a[1]), "r"(a[2]), "r"(a[3]), "r"(b[0]), "r"(b[1]));
}
__device__ __forceinline__ uint32_t packh2(float a, float b) {
    __half2 h = __floats2half2_rn(a, b);
    return *reinterpret_cast<uint32_t*>(&h);
}

// ===========================================================================
// cvt: fp32 -> fp16 (contiguous, activations)
// ===========================================================================
__global__ __launch_bounds__(256) void cvt_kernel(
    const float* __restrict__ in, __half* __restrict__ h, int n)
{
    int i = (blockIdx.x * 256 + threadIdx.x) * 8;
    if (i >= n) return;
    float4 v0 = *(const float4*)(in + i);
    float4 v1 = *(const float4*)(in + i + 4);
    *reinterpret_cast<__half2*>(h + i)     = __floats2half2_rn(v0.x, v0.y);
    *reinterpret_cast<__half2*>(h + i + 2) = __floats2half2_rn(v0.z, v0.w);
    *reinterpret_cast<__half2*>(h + i + 4) = __floats2half2_rn(v1.x, v1.y);
    *reinterpret_cast<__half2*>(h + i + 6) = __floats2half2_rn(v1.z, v1.w);
}

// ===========================================================================
// cvtw_all: converts ALL six weights into the merged fp16 buffer in one
// launch. Layout: [QKV merged 768x2304 | Wo | W1 | W2].
// ===========================================================================
__global__ __launch_bounds__(256) void cvtw_all(
    const float* __restrict__ Wq, const float* __restrict__ Wk,
    const float* __restrict__ Wv, const float* __restrict__ Wo,
    const float* __restrict__ W1, const float* __restrict__ W2,
    __half* __restrict__ wh)
{
    const size_t EE = 589824, EF = 2359296;
    size_t i = ((size_t)blockIdx.x * 256 + threadIdx.x) * 4;
    if (i >= (size_t)WTOT) return;

    const float* src;
    size_t j;
    __half* dst;
    if (i < 3 * EE) {
        int s = (int)(i / EE);
        j = i - (size_t)s * EE;
        src = (s == 0) ? Wq : (s == 1) ? Wk : Wv;
        size_t k = j / 768, n = j - k * 768;
        dst = wh + k * QKVN + (size_t)s * 768 + n;
    } else if (i < 4 * EE) {
        j = i - 3 * EE; src = Wo; dst = wh + 3 * EE + j;
    } else if (i < 4 * EE + EF) {
        j = i - 4 * EE; src = W1; dst = wh + 4 * EE + j;
    } else {
        j = i - 4 * EE - EF; src = W2; dst = wh + 4 * EE + EF + j;
    }
    float4 v = *(const float4*)(src + j);
    *reinterpret_cast<__half2*>(dst)     = __floats2half2_rn(v.x, v.y);
    *reinterpret_cast<__half2*>(dst + 2) = __floats2half2_rn(v.z, v.w);
}

// ===========================================================================
// GEMM: all outputs fp16. EPI: 2 = plain; 3 = +bias+relu; 4 = +bias
// ===========================================================================
#define ASTR 24
#define BSTR 136

template <int EPI>
__global__ __launch_bounds__(256, 2) void tgemm(
    const __half* __restrict__ A, const __half* __restrict__ B,
    const float* __restrict__ bias, __half* __restrict__ Ch,
    int M, int N, int K)
{
    __shared__ __align__(16) __half sA[2][128 * ASTR];
    __shared__ __align__(16) __half sB[2][16 * BSTR];

    const int tid  = threadIdx.x;
    const int lane = tid & 31;
    const int w    = tid >> 5;
    const int wm   = w & 3;
    const int wn   = w >> 2;
    const int bm   = blockIdx.y * 128;
    const int bn   = blockIdx.x * 128;

    const int ar  = tid >> 1;
    const int acg = (tid & 1) * 8;
    const int br  = tid >> 4;
    const int bc  = (tid & 15) * 8;

    const __half* gA = A + (size_t)(bm + ar) * K + acg;
    const __half* gB = B + (size_t)br * N + bn + bc;

    int a_off[2];
#pragma unroll
    for (int mi = 0; mi < 2; mi++) {
        int row = wm * 32 + mi * 16 + (lane & 15);
        int col = (lane >> 4) * 8;
        a_off[mi] = row * ASTR + col;
    }
    int b_off[4];
    {
        int krow = lane & 15;
#pragma unroll
        for (int p = 0; p < 4; p++) {
            int col = wn * 64 + (p * 2 + (lane >> 4)) * 8;
            b_off[p] = krow * BSTR + col;
        }
    }

    float c[2][8][4];
#pragma unroll
    for (int mi = 0; mi < 2; mi++)
#pragma unroll
        for (int ni = 0; ni < 8; ni++)
#pragma unroll
            for (int e = 0; e < 4; e++) c[mi][ni][e] = 0.f;

    const int nk = K >> 4;

    uint4 pa, pb;
    {
        uint4 va = *(const uint4*)gA;
        uint4 vb = *(const uint4*)gB;
        *(uint4*)&sA[0][ar * ASTR + acg] = va;
        *(uint4*)&sB[0][br * BSTR + bc]  = vb;
    }
    if (nk > 1) {
        pa = *(const uint4*)(gA + 16);
        pb = *(const uint4*)(gB + (size_t)16 * N);
    }
    __syncthreads();

    for (int kt = 0; kt < nk; kt++) {
        const int buf = kt & 1;

        uint32_t fa[2][4], fb[8][2];
#pragma unroll
        for (int mi = 0; mi < 2; mi++) ldsm4(fa[mi], &sA[buf][a_off[mi]]);
#pragma unroll
        for (int p = 0; p < 4; p++) {
            uint32_t r[4];
            ldsm4t(r, &sB[buf][b_off[p]]);
            fb[p * 2][0] = r[0]; fb[p * 2][1] = r[1];
            fb[p * 2 + 1][0] = r[2]; fb[p * 2 + 1][1] = r[3];
        }

        if (kt + 1 < nk) {
            const int nb = buf ^ 1;
            *(uint4*)&sA[nb][ar * ASTR + acg] = pa;
            *(uint4*)&sB[nb][br * BSTR + bc]  = pb;
        }
        if (kt + 2 < nk) {
            int k0 = (kt + 2) * 16;
            pa = *(const uint4*)(gA + k0);
            pb = *(const uint4*)(gB + (size_t)k0 * N);
        }

#pragma unroll
        for (int mi = 0; mi < 2; mi++)
#pragma unroll
            for (int ni = 0; ni < 8; ni++) mma16816(c[mi][ni], fa[mi], fb[ni]);

        if (kt + 1 < nk) __syncthreads();
    }

    const int er = lane >> 2;
    const int ec = (lane & 3) * 2;
#pragma unroll
    for (int mi = 0; mi < 2; mi++) {
#pragma unroll
        for (int ni = 0; ni < 8; ni++) {
            int r0 = bm + wm * 32 + mi * 16 + er;
            int cc = bn + wn * 64 + ni * 8 + ec;
            float v0 = c[mi][ni][0], v1 = c[mi][ni][1];
            float v2 = c[mi][ni][2], v3 = c[mi][ni][3];
            if (EPI >= 3) {
                float bi0 = bias[cc], bi1 = bias[cc + 1];
                v0 += bi0; v1 += bi1; v2 += bi0; v3 += bi1;
            }
            if (EPI == 3) {
                v0 = fmaxf(v0, 0.f); v1 = fmaxf(v1, 0.f);
                v2 = fmaxf(v2, 0.f); v3 = fmaxf(v3, 0.f);
            }
            *reinterpret_cast<__half2*>(&Ch[(size_t)r0 * N + cc]) =
                __floats2half2_rn(v0, v1);
            *reinterpret_cast<__half2*>(&Ch[(size_t)(r0 + 8) * N + cc]) =
                __floats2half2_rn(v2, v3);
        }
    }
}

// ===========================================================================
// Tensor-core attention (unchanged).
// ===========================================================================
#define FA_SMEM 101376

__global__ __launch_bounds__(256) void fattn_kernel(
    const __half* __restrict__ QKV, __half* __restrict__ Oh)
{
    extern __shared__ __half sm16[];
    __half* sQ  = sm16;
    __half* sKV = sm16 + 64 * 72;
    float*  sMax = (float*)(sm16 + 64 * 72 + 512 * 72);
    float*  sSum = sMax + 128;
    float*  sO   = sSum + 128;

    const int qt = blockIdx.x, h = blockIdx.y, b = blockIdx.z;
    const int tid = threadIdx.x, lane = tid & 31, w = tid >> 5;
    const int wm = w & 3, wn = w >> 2;
    const size_t rowbase = (size_t)b * SEQ;

    for (int i = tid; i < 512; i += 256) {
        int r = i >> 3, cc = (i & 7) * 8;
        *(uint4*)&sQ[r * 72 + cc] =
            *(const uint4*)&QKV[(rowbase + qt * 64 + r) * QKVN + h * 64 + cc];
    }
    for (int i = tid; i < 4096; i += 256) {
        int r = i >> 3, cc = (i & 7) * 8;
        *(uint4*)&sKV[r * 72 + cc] =
            *(const uint4*)&QKV[(rowbase + r) * QKVN + 768 + h * 64 + cc];
    }
    __syncthreads();

    float c[32][4];
#pragma unroll
    for (int t = 0; t < 32; t++)
#pragma unroll
        for (int e = 0; e < 4; e++) c[t][e] = 0.f;

    const int qrow   = 16 * wm + (lane & 15);
    const int bn_row = (lane & 7) + ((lane >> 4) & 1) * 8;
    const int bk_off = ((lane >> 3) & 1) * 8;

#pragma unroll
    for (int kt = 0; kt < 4; kt++) {
        uint32_t fa[4];
        ldsm4(fa, &sQ[qrow * 72 + kt * 16 + (lane >> 4) * 8]);
#pragma unroll
        for (int ng = 0; ng < 16; ng++) {
            int n0 = 256 * wn + ng * 16;
            uint32_t fb[4];
            ldsm4(fb, &sKV[(n0 + bn_row) * 72 + kt * 16 + bk_off]);
            mma16816(c[ng * 2],     fa, fb);
            mma16816(c[ng * 2 + 1], fa, fb + 2);
        }
    }

    float mx0 = -1e30f, mx1 = -1e30f;
#pragma unroll
    for (int t = 0; t < 32; t++) {
        mx0 = fmaxf(mx0, fmaxf(c[t][0], c[t][1]));
        mx1 = fmaxf(mx1, fmaxf(c[t][2], c[t][3]));
    }
    mx0 = fmaxf(mx0, __shfl_xor_sync(0xffffffffu, mx0, 1));
    mx0 = fmaxf(mx0, __shfl_xor_sync(0xffffffffu, mx0, 2));
    mx1 = fmaxf(mx1, __shfl_xor_sync(0xffffffffu, mx1, 1));
    mx1 = fmaxf(mx1, __shfl_xor_sync(0xffffffffu, mx1, 2));
    const int r_lo = 16 * wm + (lane >> 2);
    const int r_hi = r_lo + 8;
    if ((lane & 3) == 0) {
        sMax[wn * 64 + r_lo] = mx0;
        sMax[wn * 64 + r_hi] = mx1;
    }
    __syncthreads();
    const float m0 = fmaxf(sMax[r_lo], sMax[64 + r_lo]);
    const float m1 = fmaxf(sMax[r_hi], sMax[64 + r_hi]);

    for (int i = tid; i < 4096; i += 256) {
        int r = i >> 3, cc = (i & 7) * 8;
        *(uint4*)&sKV[r * 72 + cc] =
            *(const uint4*)&QKV[(rowbase + r) * QKVN + 1536 + h * 64 + cc];
    }

    const float sc = 0.125f;
    float s0 = 0.f, s1 = 0.f;
#pragma unroll
    for (int t = 0; t < 32; t++) {
        c[t][0] = __expf(sc * (c[t][0] - m0));
        c[t][1] = __expf(sc * (c[t][1] - m0));
        c[t][2] = __expf(sc * (c[t][2] - m1));
        c[t][3] = __expf(sc * (c[t][3] - m1));
        s0 += c[t][0] + c[t][1];
        s1 += c[t][2] + c[t][3];
    }
    s0 += __shfl_xor_sync(0xffffffffu, s0, 1);
    s0 += __shfl_xor_sync(0xffffffffu, s0, 2);
    s1 += __shfl_xor_sync(0xffffffffu, s1, 1);
    s1 += __shfl_xor_sync(0xffffffffu, s1, 2);
    if ((lane & 3) == 0) {
        sSum[wn * 64 + r_lo] = s0;
        sSum[wn * 64 + r_hi] = s1;
    }
    __syncthreads();
    const float inv0 = 1.0f / (sSum[r_lo] + sSum[64 + r_lo]);
    const float inv1 = 1.0f / (sSum[r_hi] + sSum[64 + r_hi]);

    uint32_t af[16][4];
#pragma unroll
    for (int ks = 0; ks < 16; ks++) {
        af[ks][0] = packh2(c[2 * ks][0],     c[2 * ks][1]);
        af[ks][1] = packh2(c[2 * ks][2],     c[2 * ks][3]);
        af[ks][2] = packh2(c[2 * ks + 1][0], c[2 * ks + 1][1]);
        af[ks][3] = packh2(c[2 * ks + 1][2], c[2 * ks + 1][3]);
    }

    float o[8][4];
#pragma unroll
    for (int nt = 0; nt < 8; nt++)
#pragma unroll
        for (int e = 0; e < 4; e++) o[nt][e] = 0.f;

    const int vk = lane & 15;
#pragma unroll
    for (int ks = 0; ks < 16; ks++) {
        const int k0 = 256 * wn + ks * 16;
#pragma unroll
        for (int p = 0; p < 4; p++) {
            uint32_t r4[4];
            ldsm4t(r4, &sKV[(k0 + vk) * 72 + (p * 2 + (lane >> 4)) * 8]);
            mma16816(o[p * 2],     af[ks], r4);
            mma16816(o[p * 2 + 1], af[ks], r4 + 2);
        }
    }

    const int er = lane >> 2;
    const int ec = (lane & 3) * 2;
    if (wn == 1) {
#pragma unroll
        for (int nt = 0; nt < 8; nt++) {
            sO[(16 * wm + er) * 68 + nt * 8 + ec]         = o[nt][0];
            sO[(16 * wm + er) * 68 + nt * 8 + ec + 1]     = o[nt][1];
            sO[(16 * wm + er + 8) * 68 + nt * 8 + ec]     = o[nt][2];
            sO[(16 * wm + er + 8) * 68 + nt * 8 + ec + 1] = o[nt][3];
        }
    }
    __syncthreads();
    if (wn == 0) {
        const size_t out_lo = (rowbase + qt * 64 + r_lo) * EMB + h * 64;
        const size_t out_hi = (rowbase + qt * 64 + r_hi) * EMB + h * 64;
#pragma unroll
        for (int nt = 0; nt < 8; nt++) {
            float v0 = (o[nt][0] + sO[r_lo * 68 + nt * 8 + ec])     * inv0;
            float v1 = (o[nt][1] + sO[r_lo * 68 + nt * 8 + ec + 1]) * inv0;
            float v2 = (o[nt][2] + sO[r_hi * 68 + nt * 8 + ec])     * inv1;
            float v3 = (o[nt][3] + sO[r_hi * 68 + nt * 8 + ec + 1]) * inv1;
            *reinterpret_cast<__half2*>(&Oh[out_lo + nt * 8 + ec]) =
                __floats2half2_rn(v0, v1);
            *reinterpret_cast<__half2*>(&Oh[out_hi + nt * 8 + ec]) =
                __floats2half2_rn(v2, v3);
        }
    }
}

// ===========================================================================
// Fused residual + LayerNorm; residual branch is fp16.
// ===========================================================================
__global__ __launch_bounds__(256) void add_ln_kernel(
    const float* __restrict__ x, const __half* __restrict__ r,
    const float* __restrict__ gamma, const float* __restrict__ beta,
    float* __restrict__ out, __half* __restrict__ oh)
{
    const int row = blockIdx.x;
    const int tid = threadIdx.x;
    const float* xr = x + (size_t)row * EMB;
    const __half* rr = r + (size_t)row * EMB;

    float v[3];
    float s = 0.f;
#pragma unroll
    for (int i = 0; i < 3; i++) {
        int cx = tid + i * 256;
        float t = xr[cx] + __half2float(rr[cx]);
        v[i] = t;
        s += t;
    }

    __shared__ float red[8];
    const int wid = tid >> 5, lane = tid & 31;
#pragma unroll
    for (int o = 16; o > 0; o >>= 1) s += __shfl_xor_sync(0xffffffffu, s, o);
    if (lane == 0) red[wid] = s;
    __syncthreads();
    if (tid == 0) {
        float t = 0.f;
#pragma unroll
        for (int i = 0; i < 8; i++) t += red[i];
        red[0] = t;
    }
    __syncthreads();
    const float mean = red[0] * (1.0f / 768.0f);

    float s2 = 0.f;
#pragma unroll
    for (int i = 0; i < 3; i++) {
        float d = v[i] - mean;
        s2 += d * d;
    }
#pragma unroll
    for (int o = 16; o > 0; o >>= 1) s2 += __shfl_xor_sync(0xffffffffu, s2, o);
    __syncthreads();
    if (lane == 0) red[wid] = s2;
    __syncthreads();
    if (tid == 0) {
        float t = 0.f;
#pragma unroll
        for (int i = 0; i < 8; i++) t += red[i];
        red[0] = t;
    }
    __syncthreads();
    const float var  = red[0] * (1.0f / 768.0f);
    const float rstd = rsqrtf(var + 1e-5f);

#pragma unroll
    for (int i = 0; i < 3; i++) {
        int cx = tid + i * 256;
        float o = (v[i] - mean) * rstd * gamma[cx] + beta[cx];
        size_t idx = (size_t)row * EMB + cx;
        out[idx] = o;
        if (oh) oh[idx] = __float2half_rn(o);
    }
}

// ===========================================================================
// Launch
// ===========================================================================
extern "C" void kernel_launch(void* const* d_in, const int* in_sizes, int n_in,
                              void* d_out, int out_size)
{
    (void)in_sizes; (void)n_in; (void)out_size;

    const float* x   = (const float*)d_in[0];
    const float* Wq  = (const float*)d_in[1];
    const float* Wk  = (const float*)d_in[2];
    const float* Wv  = (const float*)d_in[3];
    const float* Wo  = (const float*)d_in[4];
    const float* W1  = (const float*)d_in[5];
    const float* b1  = (const float*)d_in[6];
    const float* W2  = (const float*)d_in[7];
    const float* b2  = (const float*)d_in[8];
    const float* g1  = (const float*)d_in[9];
    const float* be1 = (const float*)d_in[10];
    const float* g2  = (const float*)d_in[11];
    const float* be2 = (const float*)d_in[12];
    float* out = (float*)d_out;

    float *x1;
    __half *qkv, *ah, *ch, *fh, *wh;
    cudaGetSymbolAddress((void**)&qkv, g_qkv);
    cudaGetSymbolAddress((void**)&x1,  g_x1);
    cudaGetSymbolAddress((void**)&ah,  g_ah);
    cudaGetSymbolAddress((void**)&ch,  g_ch);
    cudaGetSymbolAddress((void**)&fh,  g_fh);
    cudaGetSymbolAddress((void**)&wh,  g_wh);
    __half* tmp16 = qkv;   // g_qkv is free after attention

    cudaFuncSetAttribute(fattn_kernel,
                         cudaFuncAttributeMaxDynamicSharedMemorySize, FA_SMEM);

    const size_t EE = (size_t)EMB * EMB;
    const size_t EF = (size_t)EMB * FFND;
    const size_t OQKV = 0, OO_ = 3 * EE, O1_ = 4 * EE, O2_ = 4 * EE + EF;

    dim3 blk(256);

    // conversions: activations + ALL weights in one launch
    cvt_kernel<<<NTOK * EMB / 2048, blk>>>(x, ah, NTOK * EMB);
    cvtw_all<<<WTOT / 1024, blk>>>(Wq, Wk, Wv, Wo, W1, W2, wh);

    // fused QKV projection -> fp16
    tgemm<2><<<dim3(QKVN / 128, NTOK / 128), blk>>>(
        ah, wh + OQKV, nullptr, qkv, NTOK, QKVN, EMB);

    // tensor-core attention -> ctx (fp16)
    fattn_kernel<<<dim3(SEQ / 64, HEADS, BATCH), blk, FA_SMEM>>>(qkv, ch);

    // output projection -> fp16 tmp (reuses qkv buffer)
    tgemm<2><<<dim3(EMB / 128, NTOK / 128), blk>>>(
        ch, wh + OO_, nullptr, tmp16, NTOK, EMB, EMB);

    // residual + LN1 (emits x1 fp32 + fp16 into ah)
    add_ln_kernel<<<NTOK, blk>>>(x, tmp16, g1, be1, x1, ah);

    // FFN
    tgemm<3><<<dim3(FFND / 128, NTOK / 128), blk>>>(
        ah, wh + O1_, b1, fh, NTOK, FFND, EMB);
    tgemm<4><<<dim3(EMB / 128, NTOK / 128), blk>>>(
        fh, wh + O2_, b2, tmp16, NTOK, EMB, FFND);

    // residual + LN2
    add_ln_kernel<<<NTOK, blk>>>(x1, tmp16, g2, be2, out, nullptr);
}